// round 1
// baseline (speedup 1.0000x reference)
#include <cuda_runtime.h>

#define HW 4096
#define NR 2048
#define NL 16

// ---------------- device scratch (no allocations allowed) ----------------
__device__ float d_S[NR];                       // x-row sums
__device__ int   d_gcount[NL], d_gstart[NL];
__device__ int   d_nvalid;
__device__ int   d_prow[NR], d_pgrp[NR];        // per grouped-position
__device__ float d_pwq[NR], d_pbq[NR], d_pwk[NR], d_pbk[NR], d_pwv[NR], d_pbv[NR];
__device__ int   d_pmq[NR], d_pnk[NR], d_pnv[NR];
__device__ float d_pSq[NR], d_pSk[NR];
__device__ float d_cst[NR];
__device__ float d_scores[(long long)NR * NR];  // 16 MB: scores, then coeffs in-place

#define MAXWS 512
#define MAXWO 64
__device__ int d_wsG[MAXWS], d_wsA[MAXWS], d_wsB[MAXWS], d_nWorkS;
__device__ int d_woG[MAXWO], d_woA[MAXWO], d_nWorkO;

// ---------------- f32x2 helpers (FFMA2: 2x fp32 FMA rate on sm_103a) -----
__device__ __forceinline__ unsigned long long dup2(float v) {
    unsigned long long r;
    asm("mov.b64 %0, {%1, %1};" : "=l"(r) : "f"(v));
    return r;
}
__device__ __forceinline__ void fma2(unsigned long long &d, unsigned long long a,
                                     unsigned long long b) {
    asm("fma.rn.f32x2 %0, %1, %2, %0;" : "+l"(d) : "l"(a), "l"(b));
}
__device__ __forceinline__ float2 unpk(unsigned long long v) {
    float2 r;
    asm("mov.b64 {%0, %1}, %2;" : "=f"(r.x), "=f"(r.y) : "l"(v));
    return r;
}

// ---------------- setup kernels ----------------
__global__ void initKernel() {
    int t = threadIdx.x;
    if (t < NL) d_gcount[t] = 0;
}

__global__ void countKernel(const int* __restrict__ labels) {
    int i = blockIdx.x * blockDim.x + threadIdx.x;
    int l = labels[i];
    if (l >= 0) atomicAdd(&d_gcount[l], 1);
}

__global__ void rowsumKernel(const float* __restrict__ x) {
    int m = blockIdx.x;
    const float4* p = (const float4*)(x + (long long)m * HW);
    float s = 0.f;
    for (int i = threadIdx.x; i < HW / 4; i += 128) {
        float4 v = p[i];
        s += (v.x + v.y) + (v.z + v.w);
    }
    __shared__ float red[128];
    red[threadIdx.x] = s;
    __syncthreads();
    for (int o = 64; o > 0; o >>= 1) {
        if (threadIdx.x < o) red[threadIdx.x] += red[threadIdx.x + o];
        __syncthreads();
    }
    if (threadIdx.x == 0) d_S[m] = red[0];
}

__global__ void prefixKernel() {
    if (threadIdx.x != 0) return;
    int s = 0;
    for (int l = 0; l < NL; l++) { d_gstart[l] = s; s += d_gcount[l]; }
    d_nvalid = s;
    int n = 0;
    for (int l = 0; l < NL; l++) {
        int T = (d_gcount[l] + 127) / 128;
        for (int a = 0; a < T; a++)
            for (int b = 0; b < T; b++)
                if (n < MAXWS) { d_wsG[n] = l; d_wsA[n] = a; d_wsB[n] = b; n++; }
    }
    d_nWorkS = n;
    n = 0;
    for (int l = 0; l < NL; l++) {
        int T = (d_gcount[l] + 127) / 128;
        for (int a = 0; a < T; a++)
            if (n < MAXWO) { d_woG[n] = l; d_woA[n] = a; n++; }
    }
    d_nWorkO = n;
}

// deterministic grouping: rank by scan (2048 labels, L1-resident)
__global__ void scatterKernel(const int* __restrict__ labels,
                              const float* __restrict__ w,
                              const float* __restrict__ bb) {
    int i = blockIdx.x * blockDim.x + threadIdx.x;
    int l = labels[i];
    if (l < 0) return;
    int rank = 0;
    for (int j = 0; j < i; j++) rank += (labels[j] == l);
    int pos = d_gstart[l] + rank;
    d_prow[pos] = i;
    d_pgrp[pos] = l;
    int jq = i % 768;            int mq = (i / 768) * 256 + jq / 3;
    int rk = i + 2048; int jk = rk % 768; int nk = (rk / 768) * 256 + jk / 3;
    int rv = i + 4096; int jv = rv % 768; int nv = (rv / 768) * 256 + jv / 3;
    d_pwq[pos] = w[jq]; d_pbq[pos] = bb[jq];
    d_pwk[pos] = w[jk]; d_pbk[pos] = bb[jk];
    d_pwv[pos] = w[jv]; d_pbv[pos] = bb[jv];
    d_pmq[pos] = mq; d_pnk[pos] = nk; d_pnv[pos] = nv;
    d_pSq[pos] = d_S[mq]; d_pSk[pos] = d_S[nk];
}

// write affine part of scores: wq*bk*Sq + bq*wk*Sk + bq*bk*HW
__global__ void scoreInitKernel() {
    int p = blockIdx.x;
    if (p >= d_nvalid) return;
    int g = d_pgrp[p], gs = d_gstart[g], gc = d_gcount[g];
    float wq = d_pwq[p], bq = d_pbq[p], Sq = d_pSq[p];
    long long ro = (long long)p * NR;
    for (int bl = threadIdx.x; bl < gc; bl += 128) {
        int q = gs + bl;
        d_scores[ro + bl] = wq * d_pbk[q] * Sq + bq * d_pwk[q] * d_pSk[q]
                          + bq * d_pbk[q] * (float)HW;
    }
}

// ---------------- scores GEMM: per-group Gram, 128x128 tile, splitK=8 ----
__global__ __launch_bounds__(256) void scoresGemmKernel(const float* __restrict__ x) {
    int wi = blockIdx.x;
    if (wi >= d_nWorkS) return;
    int g = d_wsG[wi];
    int gs = d_gstart[g], gc = d_gcount[g];
    int a0 = d_wsA[wi] * 128, b0 = d_wsB[wi] * 128;
    int k0b = blockIdx.y * (HW / 8);

    __shared__ float As[8][132], Bs[8][132];
    int tid = threadIdx.x;
    int ty = tid >> 4, tx = tid & 15;

    unsigned long long acc[8][4];
#pragma unroll
    for (int r = 0; r < 8; r++)
#pragma unroll
        for (int c = 0; c < 4; c++) acc[r][c] = 0ull;

    int lr = tid >> 1, lk = (tid & 1) * 4;
    const float* ap  = (a0 + lr < gc) ? x + (long long)d_pmq[gs + a0 + lr] * HW : 0;
    const float* bpp = (b0 + lr < gc) ? x + (long long)d_pnk[gs + b0 + lr] * HW : 0;

    for (int kc = 0; kc < 64; kc++) {
        int k0 = k0b + kc * 8 + lk;
        float4 va = ap  ? *(const float4*)(ap  + k0) : make_float4(0, 0, 0, 0);
        float4 vb = bpp ? *(const float4*)(bpp + k0) : make_float4(0, 0, 0, 0);
        __syncthreads();
        As[lk + 0][lr] = va.x; As[lk + 1][lr] = va.y;
        As[lk + 2][lr] = va.z; As[lk + 3][lr] = va.w;
        Bs[lk + 0][lr] = vb.x; Bs[lk + 1][lr] = vb.y;
        Bs[lk + 2][lr] = vb.z; Bs[lk + 3][lr] = vb.w;
        __syncthreads();
#pragma unroll
        for (int kk = 0; kk < 8; kk++) {
            unsigned long long ad[8], bd[4];
#pragma unroll
            for (int r = 0; r < 8; r++) ad[r] = dup2(As[kk][ty * 8 + r]);
#pragma unroll
            for (int c = 0; c < 4; c++)
                bd[c] = *(const unsigned long long*)&Bs[kk][tx * 8 + c * 2];
#pragma unroll
            for (int r = 0; r < 8; r++)
#pragma unroll
                for (int c = 0; c < 4; c++) fma2(acc[r][c], ad[r], bd[c]);
        }
    }

#pragma unroll
    for (int r = 0; r < 8; r++) {
        int al = a0 + ty * 8 + r;
        if (al >= gc) continue;
        int p = gs + al;
        float wq = d_pwq[p];
        long long ro = (long long)p * NR;
#pragma unroll
        for (int c = 0; c < 4; c++) {
            float2 v = unpk(acc[r][c]);
            int col = b0 + tx * 8 + c * 2;
            if (col < gc)     atomicAdd(&d_scores[ro + col],     wq * d_pwk[gs + col] * v.x);
            if (col + 1 < gc) atomicAdd(&d_scores[ro + col + 1], wq * d_pwk[gs + col + 1] * v.y);
        }
    }
}

// ---------------- softmax + fold wv/bv into coefficients -----------------
__global__ void softmaxKernel() {
    int p = blockIdx.x;
    if (p >= d_nvalid) return;
    int g = d_pgrp[p], gs = d_gstart[g], gc = d_gcount[g];
    long long ro = (long long)p * NR;
    int t = threadIdx.x;
    __shared__ float red[128];

    float m = -3.4e38f;
    for (int bl = t; bl < gc; bl += 128) m = fmaxf(m, d_scores[ro + bl]);
    red[t] = m; __syncthreads();
    for (int o = 64; o > 0; o >>= 1) {
        if (t < o) red[t] = fmaxf(red[t], red[t + o]);
        __syncthreads();
    }
    m = red[0]; __syncthreads();

    float sum = 0.f, cs = 0.f;
    for (int bl = t; bl < gc; bl += 128) {
        float e = expf(d_scores[ro + bl] - m);
        d_scores[ro + bl] = e;
        sum += e;
        cs += e * d_pbv[gs + bl];
    }
    red[t] = sum; __syncthreads();
    for (int o = 64; o > 0; o >>= 1) {
        if (t < o) red[t] += red[t + o];
        __syncthreads();
    }
    sum = red[0]; __syncthreads();
    red[t] = cs; __syncthreads();
    for (int o = 64; o > 0; o >>= 1) {
        if (t < o) red[t] += red[t + o];
        __syncthreads();
    }
    cs = red[0];

    float inv = 1.0f / sum;
    for (int bl = t; bl < gc; bl += 128)
        d_scores[ro + bl] *= inv * d_pwv[gs + bl];
    if (t == 0) d_cst[p] = cs * inv;
}

// ---------------- out GEMM: coeff (g x g) @ Xv (g x 4096) ----------------
__global__ __launch_bounds__(256) void outGemmKernel(const float* __restrict__ x,
                                                     float* __restrict__ out) {
    int wi = blockIdx.x;
    if (wi >= d_nWorkO) return;
    int g = d_woG[wi];
    int gs = d_gstart[g], gc = d_gcount[g];
    int a0 = d_woA[wi] * 128;
    int t0 = blockIdx.y * 128;

    __shared__ float Cs[8][132], Xs[8][132];
    int tid = threadIdx.x, ty = tid >> 4, tx = tid & 15;

    unsigned long long acc[8][4];
#pragma unroll
    for (int r = 0; r < 8; r++)
#pragma unroll
        for (int c = 0; c < 4; c++) acc[r][c] = 0ull;

    int lr = tid >> 1, lk = (tid & 1) * 4;       // Cs loader
    int xk = tid >> 5, xc = (tid & 31) * 4;      // Xs loader
    long long crow = (a0 + lr < gc) ? (long long)(gs + a0 + lr) * NR : -1;

    for (int b0 = 0; b0 < gc; b0 += 8) {
        float4 vc = make_float4(0, 0, 0, 0);
        if (crow >= 0) {
            vc = *(const float4*)&d_scores[crow + b0 + lk];
            if (b0 + lk + 0 >= gc) vc.x = 0.f;
            if (b0 + lk + 1 >= gc) vc.y = 0.f;
            if (b0 + lk + 2 >= gc) vc.z = 0.f;
            if (b0 + lk + 3 >= gc) vc.w = 0.f;
        }
        int bm = b0 + xk;
        int vrow = (bm < gc) ? d_pnv[gs + bm] : 0;
        float4 vx = *(const float4*)&x[(long long)vrow * HW + t0 + xc];
        __syncthreads();
        Cs[lk + 0][lr] = vc.x; Cs[lk + 1][lr] = vc.y;
        Cs[lk + 2][lr] = vc.z; Cs[lk + 3][lr] = vc.w;
        *(float4*)&Xs[xk][xc] = vx;
        __syncthreads();
#pragma unroll
        for (int kk = 0; kk < 8; kk++) {
            unsigned long long ad[8], bd[4];
#pragma unroll
            for (int r = 0; r < 8; r++) ad[r] = dup2(Cs[kk][ty * 8 + r]);
#pragma unroll
            for (int c = 0; c < 4; c++)
                bd[c] = *(const unsigned long long*)&Xs[kk][tx * 8 + c * 2];
#pragma unroll
            for (int r = 0; r < 8; r++)
#pragma unroll
                for (int c = 0; c < 4; c++) fma2(acc[r][c], ad[r], bd[c]);
        }
    }

#pragma unroll
    for (int r = 0; r < 8; r++) {
        int al = a0 + ty * 8 + r;
        if (al >= gc) continue;
        int p = gs + al;
        int row = d_prow[p];
        float cst = d_cst[p];
        float* op = out + (long long)row * HW + t0 + tx * 8;
#pragma unroll
        for (int c = 0; c < 4; c++) {
            float2 v = unpk(acc[r][c]);
            op[c * 2]     = v.x + cst;
            op[c * 2 + 1] = v.y + cst;
        }
    }
}

// ---------------- launch ----------------
extern "C" void kernel_launch(void* const* d_in, const int* in_sizes, int n_in,
                              void* d_out, int out_size) {
    const float* x      = (const float*)d_in[0];
    const int*   labels = (const int*)d_in[1];
    const float* w      = (const float*)d_in[2];
    const float* bb     = (const float*)d_in[3];
    float* out = (float*)d_out;

    cudaMemsetAsync(d_out, 0, (size_t)out_size * sizeof(float), 0);
    initKernel<<<1, 32>>>();
    countKernel<<<16, 128>>>(labels);
    rowsumKernel<<<NR, 128>>>(x);
    prefixKernel<<<1, 1>>>();
    scatterKernel<<<16, 128>>>(labels, w, bb);
    scoreInitKernel<<<NR, 128>>>();
    dim3 gsGrid(512, 8);
    scoresGemmKernel<<<gsGrid, 256>>>(x);
    softmaxKernel<<<NR, 128>>>();
    dim3 goGrid(64, 32);
    outGemmKernel<<<goGrid, 256>>>(x, out);
    (void)in_sizes; (void)n_in;
}